// round 16
// baseline (speedup 1.0000x reference)
#include <cuda_runtime.h>
#include <math.h>
#include <stdint.h>

#define B 32
#define S 512
#define H 256
#define T 48
#define START_IDX 46
#define STOP_IDX 47

// Scratch (no allocations allowed): exp(emission) and emission-at-gold-tag
__device__ float g_expEm[B * S * T];    // 3 MB
__device__ float g_emAtTag[B * S];      // 64 KB

#define FMA2(acc, a, b) \
    asm("fma.rn.f32x2 %0, %1, %2, %0;" : "+l"(acc) : "l"(a), "l"(b))
#define ADD2(out, a, b) \
    asm("add.rn.f32x2 %0, %1, %2;" : "=l"(out) : "l"(a), "l"(b))
#define PACK2(out, lo, hi) \
    asm("mov.b64 %0, {%1, %2};" : "=l"(out) : "f"(lo), "f"(hi))
#define UNPACK2(lo, hi, in) \
    asm("mov.b64 {%0, %1}, %2;" : "=f"(lo), "=f"(hi) : "l"(in))

// Compiler-only ordering fence (no instruction emitted).
#define CFENCE() asm volatile("" ::: "memory")

// ---------------------------------------------------------------------------
// Kernel A: emission = feat @ W + bias; store exp(emission) and em[b,s,tags[b,s]]
// Grid: 128 blocks x 256 threads. Each block: 128 rows x 48 cols, K=256.
// ---------------------------------------------------------------------------
__global__ __launch_bounds__(256) void emis_kernel(
    const float* __restrict__ feat,   // [B*S, H]
    const float* __restrict__ Wm,     // [H, T]
    const float* __restrict__ bias,   // [T]
    const int*   __restrict__ tags)   // [B*S]
{
    const int P = 129;                       // smem pitch (conflict break)
    __shared__ float sh_W[64 * T];           // 12 KB
    __shared__ float sh_feat[64 * P];        // 33 KB  (transposed: [k][row])

    const int tid  = threadIdx.x;
    const int row0 = blockIdx.x * 128;
    const int rg   = tid >> 3;   // 0..31 -> rows rg*4..rg*4+3
    const int cg   = tid & 7;    // 0..7  -> cols cg*6..cg*6+5

    float acc[4][6];
#pragma unroll
    for (int r = 0; r < 4; r++)
#pragma unroll
        for (int c = 0; c < 6; c++) acc[r][c] = 0.0f;

    for (int kc = 0; kc < H; kc += 64) {
        for (int u = tid; u < 64 * T; u += 256) sh_W[u] = Wm[kc * T + u];

#pragma unroll
        for (int m = 0; m < 8; m++) {
            int u   = tid + m * 256;      // 0..2047
            int row = u >> 4;             // 0..127
            int k4  = u & 15;             // 0..15 (float4 index)
            float4 v = reinterpret_cast<const float4*>(feat)
                        [(size_t)(row0 + row) * (H / 4) + (kc >> 2) + k4];
            sh_feat[(k4 * 4 + 0) * P + row] = v.x;
            sh_feat[(k4 * 4 + 1) * P + row] = v.y;
            sh_feat[(k4 * 4 + 2) * P + row] = v.z;
            sh_feat[(k4 * 4 + 3) * P + row] = v.w;
        }
        __syncthreads();

#pragma unroll 16
        for (int k = 0; k < 64; k++) {
            float f0 = sh_feat[k * P + rg * 4 + 0];
            float f1 = sh_feat[k * P + rg * 4 + 1];
            float f2 = sh_feat[k * P + rg * 4 + 2];
            float f3 = sh_feat[k * P + rg * 4 + 3];
            float2 w01 = *reinterpret_cast<const float2*>(&sh_W[k * T + cg * 6 + 0]);
            float2 w23 = *reinterpret_cast<const float2*>(&sh_W[k * T + cg * 6 + 2]);
            float2 w45 = *reinterpret_cast<const float2*>(&sh_W[k * T + cg * 6 + 4]);
            float w[6] = {w01.x, w01.y, w23.x, w23.y, w45.x, w45.y};
            float f[4] = {f0, f1, f2, f3};
#pragma unroll
            for (int r = 0; r < 4; r++)
#pragma unroll
                for (int c = 0; c < 6; c++)
                    acc[r][c] = fmaf(f[r], w[c], acc[r][c]);
        }
        __syncthreads();
    }

#pragma unroll
    for (int rr = 0; rr < 4; rr++) {
        int row = row0 + rg * 4 + rr;
        int tag = __ldg(&tags[row]);
#pragma unroll
        for (int cc = 0; cc < 6; cc++) {
            int c = cg * 6 + cc;
            float em = acc[rr][cc] + __ldg(&bias[c]);
            g_expEm[(size_t)row * T + c] = expf(em);
            if (c == tag) g_emAtTag[row] = em;
        }
    }
}

// ---------------------------------------------------------------------------
// Kernel B: forward recursion, TWO independent sequences per warp (in-stream
// ILP: the two 330-cy dependency chains overlap inside one instruction
// stream; warp is alone on its SMSP so no issue-port sharing).
// Grid: 16 blocks x 32 threads; warp handles batches blockIdx.x and
// blockIdx.x+16. Lane l owns tags j0=l, j1=l+32 for BOTH sequences.
// eT2a/eT2b (transition matrix, 96 regs) shared across both batches.
// Per-batch uniform predicates freeze a finished sequence (no store, no
// measure, no E update) == reference's where(t<lengths).
// ---------------------------------------------------------------------------

// One double-step. PH compile-time (0..3); MEASURE at PH==3.
#define STEP2(sv, PH, MEASURE) do {                                           \
    const bool p0 = (sv) < len0;   /* warp-uniform */                         \
    const bool p1 = (sv) < len1;                                              \
    const ulonglong2* ava = reinterpret_cast<const ulonglong2*>(awa[buf]);    \
    const ulonglong2* avb = reinterpret_cast<const ulonglong2*>(awb[buf]);    \
    unsigned long long A0=0ull,A1=0ull,A2=0ull,A3=0ull;                       \
    unsigned long long B0=0ull,B1=0ull,B2=0ull,B3=0ull;                       \
    unsigned long long C0=0ull,C1=0ull,C2=0ull,C3=0ull;                       \
    unsigned long long D0=0ull,D1=0ull,D2=0ull,D3=0ull;                       \
    _Pragma("unroll")                                                         \
    for (int q = 0; q < 12; q += 2) {                                         \
        ulonglong2 ua = ava[q];                                               \
        ulonglong2 va = ava[q + 1];                                           \
        ulonglong2 ub = avb[q];                                               \
        ulonglong2 vb = avb[q + 1];                                           \
        FMA2(A0, ua.x, eT2a[2*q+0]); FMA2(A1, ua.y, eT2a[2*q+1]);             \
        FMA2(C0, ub.x, eT2a[2*q+0]); FMA2(C1, ub.y, eT2a[2*q+1]);             \
        FMA2(A2, va.x, eT2a[2*q+2]); FMA2(A3, va.y, eT2a[2*q+3]);             \
        FMA2(C2, vb.x, eT2a[2*q+2]); FMA2(C3, vb.y, eT2a[2*q+3]);             \
        FMA2(B0, ua.x, eT2b[2*q+0]); FMA2(B1, ua.y, eT2b[2*q+1]);             \
        FMA2(D0, ub.x, eT2b[2*q+0]); FMA2(D1, ub.y, eT2b[2*q+1]);             \
        FMA2(B2, va.x, eT2b[2*q+2]); FMA2(B3, va.y, eT2b[2*q+3]);             \
        FMA2(D2, vb.x, eT2b[2*q+2]); FMA2(D3, vb.y, eT2b[2*q+3]);             \
    }                                                                         \
    unsigned long long tA, tA2, tB, tB2, tC, tC2, tD, tD2;                    \
    ADD2(tA, A0, A1); ADD2(tA2, A2, A3); ADD2(tA, tA, tA2);                   \
    ADD2(tB, B0, B1); ADD2(tB2, B2, B3); ADD2(tB, tB, tB2);                   \
    ADD2(tC, C0, C1); ADD2(tC2, C2, C3); ADD2(tC, tC, tC2);                   \
    ADD2(tD, D0, D1); ADD2(tD2, D2, D3); ADD2(tD, tD, tD2);                   \
    float xl, xh, yl, yh;                                                     \
    UNPACK2(xl, xh, tA); UNPACK2(yl, yh, tB);                                 \
    float val0a = E0a[PH] * (xl + xh) * invMa;                                \
    float val1a = E1a[PH] * (yl + yh) * invMa;                                \
    UNPACK2(xl, xh, tC); UNPACK2(yl, yh, tD);                                 \
    float val0b = E0b[PH] * (xl + xh) * invMb;                                \
    float val1b = E1b[PH] * (yl + yh) * invMb;                                \
    invMa = 1.0f; invMb = 1.0f;                                               \
    {                                                                         \
        int sp = (sv) + 4;                                                    \
        E0a[PH] = (sp < len0) ? pe0a[(size_t)sp * T] : 0.0f;                  \
        E1a[PH] = (act1 && sp < len0) ? pe1a[(size_t)sp * T] : 0.0f;          \
        E0b[PH] = (sp < len1) ? pe0b[(size_t)sp * T] : 0.0f;                  \
        E1b[PH] = (act1 && sp < len1) ? pe1b[(size_t)sp * T] : 0.0f;          \
    }                                                                         \
    const int nb = buf ^ 1;                                                   \
    if (p0) { awa[nb][l] = val0a; awa[nb][l + 32] = val1a; }                  \
    if (p1) { awb[nb][l] = val0b; awb[nb][l + 32] = val1b; }                  \
    if (MEASURE && p0) {                                                      \
        uint32_t vb_ = __float_as_uint(fmaxf(val0a, val1a));                  \
        uint32_t wmax;                                                        \
        asm volatile("redux.sync.max.u32 %0, %1, 0xffffffff;"                 \
                     : "=r"(wmax) : "r"(vb_));                                \
        int k = (int)(wmax >> 23) - 127;                                      \
        invMa  = __uint_as_float((uint32_t)(127 - k) << 23);                  \
        Ka    += k;                                                           \
        klasta = k;                                                           \
    }                                                                         \
    if (MEASURE && p1) {                                                      \
        uint32_t vb_ = __float_as_uint(fmaxf(val0b, val1b));                  \
        uint32_t wmax;                                                        \
        asm volatile("redux.sync.max.u32 %0, %1, 0xffffffff;"                 \
                     : "=r"(wmax) : "r"(vb_));                                \
        int k = (int)(wmax >> 23) - 127;                                      \
        invMb  = __uint_as_float((uint32_t)(127 - k) << 23);                  \
        Kb    += k;                                                           \
        klastb = k;                                                           \
    }                                                                         \
    CFENCE();                                                                 \
    buf = nb;                                                                 \
} while (0)

__global__ __launch_bounds__(32) void fwd_kernel(
    const float* __restrict__ trans,     // [T,T]
    const int*   __restrict__ lengths,   // [B]
    const int*   __restrict__ tags,      // [B,S]
    float*       __restrict__ out)       // [B]
{
    __shared__ float sh_trans[T * T];
    __shared__ __align__(16) float awa[2][64];   // batch A double buffer
    __shared__ __align__(16) float awb[2][64];   // batch B double buffer

    const int l  = threadIdx.x;          // lane 0..31
    const int b0 = blockIdx.x;           // first batch
    const int b1 = blockIdx.x + B / 2;   // second batch
    const int j0 = l;                    // always < 48
    const int j1 = l + 32;               // valid tag only if < 48 (l < 16)
    const bool act1 = (j1 < T);

    for (int u = l; u < T * T; u += 32) sh_trans[u] = trans[u];
    __syncwarp();

    // transition columns j0 and j1 in registers (SHARED by both batches)
    unsigned long long eT2a[T / 2], eT2b[T / 2];
    float eStop0, eStop1 = 0.0f;
#pragma unroll
    for (int i = 0; i < T / 2; i++) {
        float lo = expf(sh_trans[(2 * i + 0) * T + j0]);
        float hi = expf(sh_trans[(2 * i + 1) * T + j0]);
        PACK2(eT2a[i], lo, hi);
    }
    eStop0 = expf(sh_trans[j0 * T + STOP_IDX]);
    if (act1) {
#pragma unroll
        for (int i = 0; i < T / 2; i++) {
            float lo = expf(sh_trans[(2 * i + 0) * T + j1]);
            float hi = expf(sh_trans[(2 * i + 1) * T + j1]);
            PACK2(eT2b[i], lo, hi);
        }
        eStop1 = expf(sh_trans[j1 * T + STOP_IDX]);
    } else {
#pragma unroll
        for (int i = 0; i < T / 2; i++) eT2b[i] = 0ull;
    }

    // START_IDX=46 lives in the UPPER slot (lane 14, j1=46)
    awa[0][l]      = (j0 == START_IDX) ? 1.0f : 0.0f;
    awa[0][l + 32] = (j1 == START_IDX) ? 1.0f : 0.0f;
    awb[0][l]      = (j0 == START_IDX) ? 1.0f : 0.0f;
    awb[0][l + 32] = (j1 == START_IDX) ? 1.0f : 0.0f;
    __syncwarp();

    const int len0 = lengths[b0];
    const int len1 = lengths[b1];
    const int lmax = max(len0, len1);

    const float* pe0a = g_expEm + (size_t)b0 * S * T + j0;
    const float* pe1a = g_expEm + (size_t)b0 * S * T + j1;
    const float* pe0b = g_expEm + (size_t)b1 * S * T + j0;
    const float* pe1b = g_expEm + (size_t)b1 * S * T + j1;

    // expEm prefetch rings, depth 4 (register-resident; len >= S/2 >= 4)
    float E0a[4], E1a[4], E0b[4], E1b[4];
#pragma unroll
    for (int q = 0; q < 4; q++) {
        E0a[q] = pe0a[(size_t)q * T];
        E1a[q] = pe1a[(size_t)q * T];
        E0b[q] = pe0b[(size_t)q * T];
        E1b[q] = pe1b[(size_t)q * T];
    }

    int   Ka = 0,    Kb = 0;       // shifted-out exponents (exact)
    int   klasta = 0, klastb = 0;  // last measure (tail fixup)
    int   buf = 0;
    float invMa = 1.0f, invMb = 1.0f;

    int s = 0;
    for (; s + 4 <= lmax; s += 4) {
        STEP2(s + 0, 0, false);
        STEP2(s + 1, 1, false);
        STEP2(s + 2, 2, false);
        STEP2(s + 3, 3, true);
    }
    if (s + 0 < lmax) STEP2(s + 0, 0, false);
    if (s + 1 < lmax) STEP2(s + 1, 1, false);
    if (s + 2 < lmax) STEP2(s + 2, 2, false);

    // if a sequence ended on a measure step, its rescale was never applied
    if ((len0 & 3) == 0) Ka -= klasta;
    if ((len1 & 3) == 0) Kb -= klastb;

    __syncwarp();   // real sync before terminal cross-lane reads

    // terminal per batch: logZ = K*ln2 + log( sum_j a[j]*exp(trans[j][STOP]) )
    const float* afa = awa[len0 & 1];
    const float* afb = awb[len1 & 1];
    float ta = afa[l] * eStop0 + afa[l + 32] * eStop1;
    float tb = afb[l] * eStop0 + afb[l + 32] * eStop1;
#pragma unroll
    for (int o = 16; o; o >>= 1) {
        ta += __shfl_xor_sync(0xffffffffu, ta, o);
        tb += __shfl_xor_sync(0xffffffffu, tb, o);
    }
    const float logZa = (float)Ka * 0.6931471805599453f + logf(ta);
    const float logZb = (float)Kb * 0.6931471805599453f + logf(tb);

    // gold scores
    const int* btags0 = tags + b0 * S;
    const int* btags1 = tags + b1 * S;
    float ga = 0.0f, gb = 0.0f;
    for (int t = l; t < len0; t += 32) {
        int to   = btags0[t];
        int from = (t == 0) ? START_IDX : btags0[t - 1];
        ga += sh_trans[from * T + to] + g_emAtTag[(size_t)b0 * S + t];
    }
    for (int t = l; t < len1; t += 32) {
        int to   = btags1[t];
        int from = (t == 0) ? START_IDX : btags1[t - 1];
        gb += sh_trans[from * T + to] + g_emAtTag[(size_t)b1 * S + t];
    }
#pragma unroll
    for (int o = 16; o; o >>= 1) {
        ga += __shfl_xor_sync(0xffffffffu, ga, o);
        gb += __shfl_xor_sync(0xffffffffu, gb, o);
    }

    if (l == 0) {
        out[b0] = logZa - (ga + sh_trans[btags0[len0 - 1] * T + STOP_IDX]);
        out[b1] = logZb - (gb + sh_trans[btags1[len1 - 1] * T + STOP_IDX]);
    }
}

// ---------------------------------------------------------------------------
extern "C" void kernel_launch(void* const* d_in, const int* in_sizes, int n_in,
                              void* d_out, int out_size)
{
    const float* feat    = (const float*)d_in[0];  // lstm_features [B,S,H]
    const float* Wm      = (const float*)d_in[1];  // emission_w [H,T]
    const float* bias    = (const float*)d_in[2];  // emission_b [T]
    const float* trans   = (const float*)d_in[3];  // transitions [T,T]
    const int*   lengths = (const int*)d_in[4];    // [B]
    const int*   tags    = (const int*)d_in[5];    // [B,S]
    float*       out     = (float*)d_out;          // [B]

    emis_kernel<<<(B * S) / 128, 256>>>(feat, Wm, bias, tags);
    fwd_kernel<<<B / 2, 32>>>(trans, lengths, tags, out);
}